// round 16
// baseline (speedup 1.0000x reference)
#include <cuda_runtime.h>
#include <cuda_bf16.h>
#include <math.h>
#include <stdint.h>

#define SA 272u   // padded smem row stride in bytes (128 bf16 + 16B pad)
#define NT 512    // threads per CTA (16 warps, 4 row-groups)

// f32 h after stage 2 (needed for the irregular parent gather). 128 MiB static.
__device__ float g_H[64u * 4096u * 128u];

// ---------------------------------------------------------------------------
static __device__ __forceinline__ uint32_t s2u(const void* p) {
    uint32_t a;
    asm("{ .reg .u64 t; cvta.to.shared.u64 t, %1; cvt.u32.u64 %0, t; }" : "=r"(a) : "l"(p));
    return a;
}
static __device__ __forceinline__ void barg(int id) {
    asm volatile("bar.sync %0, 128;" :: "r"(id) : "memory");
}
static __device__ __forceinline__ void ldsm4(uint32_t& r0, uint32_t& r1, uint32_t& r2,
                                             uint32_t& r3, uint32_t addr) {
    asm volatile("ldmatrix.sync.aligned.m8n8.x4.shared.b16 {%0,%1,%2,%3}, [%4];"
                 : "=r"(r0), "=r"(r1), "=r"(r2), "=r"(r3) : "r"(addr));
}
static __device__ __forceinline__ void mma16816(float* c, const uint32_t* a,
                                                uint32_t b0, uint32_t b1) {
    asm volatile("mma.sync.aligned.m16n8k16.row.col.f32.bf16.bf16.f32 "
                 "{%0,%1,%2,%3},{%4,%5,%6,%7},{%8,%9},{%0,%1,%2,%3};"
                 : "+f"(c[0]), "+f"(c[1]), "+f"(c[2]), "+f"(c[3])
                 : "r"(a[0]), "r"(a[1]), "r"(a[2]), "r"(a[3]), "r"(b0), "r"(b1));
}
// fast ELU: exp via single MUFU.EX2 (__expf). |abs err| ~1e-7, fine vs 1e-3 gate.
static __device__ __forceinline__ float elu1(float v) {
    return v > 0.0f ? v : (__expf(v) - 1.0f);
}
static __device__ __forceinline__ uint32_t pack2(__nv_bfloat16 a, __nv_bfloat16 b) {
    __nv_bfloat162 t = __halves2bfloat162(a, b);
    return *(uint32_t*)&t;
}
static __device__ __forceinline__ void split2(float a, float b, uint32_t& hi, uint32_t& lo) {
    __nv_bfloat16 ha = __float2bfloat16(a), hb = __float2bfloat16(b);
    __nv_bfloat16 la = __float2bfloat16(a - __bfloat162float(ha));
    __nv_bfloat16 lb = __float2bfloat16(b - __bfloat162float(hb));
    hi = pack2(ha, hb);
    lo = pack2(la, lb);
}
__device__ __forceinline__ float warp_sum(float v) {
#pragma unroll
    for (int o = 16; o; o >>= 1) v += __shfl_xor_sync(0xffffffffu, v, o);
    return v;
}
__device__ __forceinline__ float warp_max(float v) {
#pragma unroll
    for (int o = 16; o; o >>= 1) v = fmaxf(v, __shfl_xor_sync(0xffffffffu, v, o));
    return v;
}
static __device__ __forceinline__ float qsum(float v) {
    v += __shfl_xor_sync(0xffffffffu, v, 1);
    v += __shfl_xor_sync(0xffffffffu, v, 2);
    return v;
}

// Merged 3-product hi/lo GEMM over K=128. Single kt loop; every A/B smem datum
// is loaded exactly once (64 ldsm4 total): per kt load Bh,Bl,Ah,Al fragments,
// then issue Ah*Bh + Al*Bh + Ah*Bl from registers. (Al*Bl dropped: ~2^-18 rel.)
static __device__ __forceinline__ void gemm3(uint32_t aHi, uint32_t aLo,
                                             uint32_t wHi, uint32_t wLo,
                                             float c[2][4][4], int mrow0, int ncol0,
                                             int lane) {
    const int arow = ((lane >> 3) & 1) * 8 + (lane & 7);
    const int acol = ((lane >> 4) & 1) * 8;
    const int brow = ((lane >> 4) & 1) * 8 + (lane & 7);
    const int bcol = ((lane >> 3) & 1) * 8;
#pragma unroll
    for (int kt = 0; kt < 8; kt++) {
        uint32_t bh[4][2], bl[4][2];
#pragma unroll
        for (int np = 0; np < 2; np++) {
            const uint32_t boffs = (uint32_t)(ncol0 + np * 16 + brow) * SA + (kt * 16 + bcol) * 2;
            ldsm4(bh[2 * np][0], bh[2 * np][1], bh[2 * np + 1][0], bh[2 * np + 1][1], wHi + boffs);
            ldsm4(bl[2 * np][0], bl[2 * np][1], bl[2 * np + 1][0], bl[2 * np + 1][1], wLo + boffs);
        }
#pragma unroll
        for (int mt = 0; mt < 2; mt++) {
            const uint32_t aoffs = (uint32_t)(mrow0 + mt * 16 + arow) * SA + (kt * 16 + acol) * 2;
            uint32_t ah[4], al[4];
            ldsm4(ah[0], ah[1], ah[2], ah[3], aHi + aoffs);
            ldsm4(al[0], al[1], al[2], al[3], aLo + aoffs);
#pragma unroll
            for (int nt = 0; nt < 4; nt++) mma16816(c[mt][nt], ah, bh[nt][0], bh[nt][1]);
#pragma unroll
            for (int nt = 0; nt < 4; nt++) mma16816(c[mt][nt], al, bh[nt][0], bh[nt][1]);
#pragma unroll
            for (int nt = 0; nt < 4; nt++) mma16816(c[mt][nt], ah, bl[nt][0], bl[nt][1]);
        }
    }
}

// ---------------------------------------------------------------------------
// k_mlp smem layout (bytes)
#define M_AHI 0u
#define M_ALO 34816u
#define M_W1H 69632u
#define M_W1L 104448u
#define M_W2H 139264u
#define M_W2L 174080u
#define M_PRM 208896u
#define M_RED 211968u
#define M_TOT 216064u

__global__ __launch_bounds__(NT, 1)
void k_mlp(const float* __restrict__ x,
           const float* __restrict__ W1, const float* __restrict__ b1,
           const float* __restrict__ g1, const float* __restrict__ be1,
           const float* __restrict__ W2, const float* __restrict__ b2,
           const float* __restrict__ g2, const float* __restrict__ be2,
           int nrows)
{
    extern __shared__ char smem[];
    const uint32_t sb = s2u(smem);
    float* prm = (float*)(smem + M_PRM);
    float* red = (float*)(smem + M_RED);
    const int tid = threadIdx.x, w = tid >> 5, lane = tid & 31;
    const int grp = tid >> 7;                // row-group 0..3
    const int tig = tid & 127;               // tid within group
    const int mrow0 = grp * 32, quar = w & 3, ncol0 = quar * 32;
    const int barid = 1 + grp;

    // Weights: Wt[n][k] bf16 hi/lo, padded rows
    for (int idx = tid; idx < 16384; idx += NT) {
        const int k = idx >> 7, n = idx & 127;
        float wv = W1[idx];
        __nv_bfloat16 h = __float2bfloat16(wv);
        *(__nv_bfloat16*)(smem + M_W1H + n * SA + k * 2) = h;
        *(__nv_bfloat16*)(smem + M_W1L + n * SA + k * 2) = __float2bfloat16(wv - __bfloat162float(h));
        wv = W2[idx];
        h = __float2bfloat16(wv);
        *(__nv_bfloat16*)(smem + M_W2H + n * SA + k * 2) = h;
        *(__nv_bfloat16*)(smem + M_W2L + n * SA + k * 2) = __float2bfloat16(wv - __bfloat162float(h));
    }
    if (tid < 128) {
        prm[tid]       = b1[tid];
        prm[128 + tid] = g1[tid];
        prm[256 + tid] = be1[tid];
        prm[384 + tid] = b2[tid];
        prm[512 + tid] = g2[tid];
        prm[640 + tid] = be2[tid];
    }
    __syncthreads();

    const float4* x4 = (const float4*)x;
    const int ntiles = nrows >> 7;

    for (int t = blockIdx.x; t < ntiles; t += gridDim.x) {
        const long row0g = (long)t << 7;

        // ---- group loads its 32 rows of x -> A_hi/A_lo ----
        for (int i = tig; i < 1024; i += 128) {
            const int r = i >> 5, c4 = i & 31;       // r in [0,32)
            const float4 v = x4[(row0g + mrow0 + r) * 32 + c4];
            uint2 uh, ul;
            split2(v.x, v.y, uh.x, ul.x);
            split2(v.z, v.w, uh.y, ul.y);
            *(uint2*)(smem + M_AHI + (mrow0 + r) * SA + c4 * 8) = uh;
            *(uint2*)(smem + M_ALO + (mrow0 + r) * SA + c4 * 8) = ul;
        }
        barg(barid);   // (1)

        // ---- GEMM1 ----
        float c[2][4][4];
#pragma unroll
        for (int mt = 0; mt < 2; mt++)
#pragma unroll
            for (int nt = 0; nt < 4; nt++)
#pragma unroll
                for (int e = 0; e < 4; e++) c[mt][nt][e] = 0.0f;
        gemm3(sb + M_AHI, sb + M_ALO, sb + M_W1H, sb + M_W1L, c, mrow0, ncol0, lane);

        // ---- epilogue 1: bias + LN stats ----
        {
            float s[2][2] = {{0, 0}, {0, 0}}, sq[2][2] = {{0, 0}, {0, 0}};
#pragma unroll
            for (int mt = 0; mt < 2; mt++)
#pragma unroll
                for (int nt = 0; nt < 4; nt++) {
                    const int col0 = ncol0 + nt * 8 + (lane & 3) * 2;
                    float v0 = c[mt][nt][0] + prm[col0];
                    float v1 = c[mt][nt][1] + prm[col0 + 1];
                    float v2 = c[mt][nt][2] + prm[col0];
                    float v3 = c[mt][nt][3] + prm[col0 + 1];
                    c[mt][nt][0] = v0; c[mt][nt][1] = v1;
                    c[mt][nt][2] = v2; c[mt][nt][3] = v3;
                    s[mt][0] += v0 + v1;  sq[mt][0] += v0 * v0 + v1 * v1;
                    s[mt][1] += v2 + v3;  sq[mt][1] += v2 * v2 + v3 * v3;
                }
#pragma unroll
            for (int mt = 0; mt < 2; mt++)
#pragma unroll
                for (int rh = 0; rh < 2; rh++) {
                    s[mt][rh] = qsum(s[mt][rh]);
                    sq[mt][rh] = qsum(sq[mt][rh]);
                }
            if ((lane & 3) == 0) {
#pragma unroll
                for (int mt = 0; mt < 2; mt++)
#pragma unroll
                    for (int rh = 0; rh < 2; rh++) {
                        const int row = mrow0 + mt * 16 + rh * 8 + (lane >> 2);
                        red[row * 8 + quar * 2]     = s[mt][rh];
                        red[row * 8 + quar * 2 + 1] = sq[mt][rh];
                    }
            }
            barg(barid);   // (2)
            float mu[2][2], rs[2][2];
#pragma unroll
            for (int mt = 0; mt < 2; mt++)
#pragma unroll
                for (int rh = 0; rh < 2; rh++) {
                    const int row = mrow0 + mt * 16 + rh * 8 + (lane >> 2);
                    const float ts = red[row * 8] + red[row * 8 + 2] + red[row * 8 + 4] + red[row * 8 + 6];
                    const float tq = red[row * 8 + 1] + red[row * 8 + 3] + red[row * 8 + 5] + red[row * 8 + 7];
                    const float m = ts * 0.0078125f;
                    mu[mt][rh] = m;
                    rs[mt][rh] = rsqrtf(tq * 0.0078125f - m * m + 1e-5f);
                }
            // normalize + ELU -> A_hi/A_lo
#pragma unroll
            for (int mt = 0; mt < 2; mt++)
#pragma unroll
                for (int nt = 0; nt < 4; nt++) {
                    const int col0 = ncol0 + nt * 8 + (lane & 3) * 2;
#pragma unroll
                    for (int rh = 0; rh < 2; rh++) {
                        const int row = mrow0 + mt * 16 + rh * 8 + (lane >> 2);
                        const float y0 = elu1((c[mt][nt][2 * rh]     - mu[mt][rh]) * rs[mt][rh] * prm[128 + col0]     + prm[256 + col0]);
                        const float y1 = elu1((c[mt][nt][2 * rh + 1] - mu[mt][rh]) * rs[mt][rh] * prm[128 + col0 + 1] + prm[256 + col0 + 1]);
                        uint32_t hh, ll;
                        split2(y0, y1, hh, ll);
                        *(uint32_t*)(smem + M_AHI + row * SA + col0 * 2) = hh;
                        *(uint32_t*)(smem + M_ALO + row * SA + col0 * 2) = ll;
                    }
                }
        }
        barg(barid);   // (3)

        // ---- GEMM2 ----
#pragma unroll
        for (int mt = 0; mt < 2; mt++)
#pragma unroll
            for (int nt = 0; nt < 4; nt++)
#pragma unroll
                for (int e = 0; e < 4; e++) c[mt][nt][e] = 0.0f;
        gemm3(sb + M_AHI, sb + M_ALO, sb + M_W2H, sb + M_W2L, c, mrow0, ncol0, lane);

        // ---- epilogue 2: bias + LN + ELU -> g_H (direct) ----
        {
            float s[2][2] = {{0, 0}, {0, 0}}, sq[2][2] = {{0, 0}, {0, 0}};
#pragma unroll
            for (int mt = 0; mt < 2; mt++)
#pragma unroll
                for (int nt = 0; nt < 4; nt++) {
                    const int col0 = ncol0 + nt * 8 + (lane & 3) * 2;
                    float v0 = c[mt][nt][0] + prm[384 + col0];
                    float v1 = c[mt][nt][1] + prm[384 + col0 + 1];
                    float v2 = c[mt][nt][2] + prm[384 + col0];
                    float v3 = c[mt][nt][3] + prm[384 + col0 + 1];
                    c[mt][nt][0] = v0; c[mt][nt][1] = v1;
                    c[mt][nt][2] = v2; c[mt][nt][3] = v3;
                    s[mt][0] += v0 + v1;  sq[mt][0] += v0 * v0 + v1 * v1;
                    s[mt][1] += v2 + v3;  sq[mt][1] += v2 * v2 + v3 * v3;
                }
#pragma unroll
            for (int mt = 0; mt < 2; mt++)
#pragma unroll
                for (int rh = 0; rh < 2; rh++) {
                    s[mt][rh] = qsum(s[mt][rh]);
                    sq[mt][rh] = qsum(sq[mt][rh]);
                }
            if ((lane & 3) == 0) {
#pragma unroll
                for (int mt = 0; mt < 2; mt++)
#pragma unroll
                    for (int rh = 0; rh < 2; rh++) {
                        const int row = mrow0 + mt * 16 + rh * 8 + (lane >> 2);
                        red[row * 8 + quar * 2]     = s[mt][rh];
                        red[row * 8 + quar * 2 + 1] = sq[mt][rh];
                    }
            }
            barg(barid);   // (4) — also signals GEMM2 A-reads complete
#pragma unroll
            for (int mt = 0; mt < 2; mt++)
#pragma unroll
                for (int rh = 0; rh < 2; rh++) {
                    const int row = mrow0 + mt * 16 + rh * 8 + (lane >> 2);
                    const float ts = red[row * 8] + red[row * 8 + 2] + red[row * 8 + 4] + red[row * 8 + 6];
                    const float tq = red[row * 8 + 1] + red[row * 8 + 3] + red[row * 8 + 5] + red[row * 8 + 7];
                    const float m = ts * 0.0078125f;
                    const float r = rsqrtf(tq * 0.0078125f - m * m + 1e-5f);
                    float* grow = g_H + (row0g + row) * 128;
#pragma unroll
                    for (int nt = 0; nt < 4; nt++) {
                        const int col0 = ncol0 + nt * 8 + (lane & 3) * 2;
                        const float o0 = elu1((c[mt][nt][2 * rh]     - m) * r * prm[512 + col0]     + prm[640 + col0]);
                        const float o1 = elu1((c[mt][nt][2 * rh + 1] - m) * r * prm[512 + col0 + 1] + prm[640 + col0 + 1]);
                        *(float2*)(grow + col0) = make_float2(o0, o1);
                    }
                }
        }
        // next-tile A overwrite is safe: barrier (4) ordered all GEMM2 reads.
    }
}

// ---------------------------------------------------------------------------
// k_edge smem layout (whole-CTA structure)
#define E_AHI 0u
#define E_ALO 34816u
#define E_WH  69632u
#define E_WL  104448u
#define E_PRM 139264u
#define E_RED 141312u
#define E_RDD 145408u
#define E_TOT 147456u

__global__ __launch_bounds__(NT, 1)
void k_edge(const int* __restrict__ pidx,
            const float* __restrict__ Wr1, const float* __restrict__ br1,
            const float* __restrict__ gr1, const float* __restrict__ ber1,
            const float* __restrict__ Wr2, const float* __restrict__ br2,
            float* __restrict__ out, int nedges, int Nm1, int N)
{
    extern __shared__ char smem[];
    const uint32_t sb = s2u(smem);
    float* prm = (float*)(smem + E_PRM);
    float* red = (float*)(smem + E_RED);
    float* rdd = (float*)(smem + E_RDD);
    const int tid = threadIdx.x, w = tid >> 5, lane = tid & 31;
    const int mrow0 = (w >> 2) * 32, quar = w & 3, ncol0 = quar * 32;

    for (int idx = tid; idx < 16384; idx += NT) {
        const int k = idx >> 7, n = idx & 127;
        const float wv = Wr1[idx];
        const __nv_bfloat16 h = __float2bfloat16(wv);
        *(__nv_bfloat16*)(smem + E_WH + n * SA + k * 2) = h;
        *(__nv_bfloat16*)(smem + E_WL + n * SA + k * 2) = __float2bfloat16(wv - __bfloat162float(h));
    }
    if (tid < 128) {
        prm[tid]       = br1[tid];
        prm[128 + tid] = gr1[tid];
        prm[256 + tid] = ber1[tid];
        prm[384 + tid] = Wr2[tid];
    }
    __syncthreads();

    const float br2v = br2[0];
    const float4* gh4 = (const float4*)g_H;
    const int ntiles = (nedges + 127) >> 7;

    for (int t = blockIdx.x; t < ntiles; t += gridDim.x) {
        const long base = (long)t << 7;

        // ---- gather + max -> A_hi/A_lo (warp w handles rows 8w..8w+7) ----
#pragma unroll
        for (int r8 = 0; r8 < 8; r8++) {
            const int row = w * 8 + r8;
            long i = base + row;
            if (i >= nedges) i = nedges - 1;
            const int b = (int)(i / Nm1);
            const long crow = (long)b * N + (int)(i - (long)b * Nm1);
            const long prow = (long)pidx[i];
            const float4 c4v = gh4[crow * 32 + lane];
            const float4 p4v = gh4[prow * 32 + lane];
            uint2 uh, ul;
            split2(fmaxf(c4v.x, p4v.x), fmaxf(c4v.y, p4v.y), uh.x, ul.x);
            split2(fmaxf(c4v.z, p4v.z), fmaxf(c4v.w, p4v.w), uh.y, ul.y);
            *(uint2*)(smem + E_AHI + row * SA + lane * 8) = uh;
            *(uint2*)(smem + E_ALO + row * SA + lane * 8) = ul;
        }
        __syncthreads();   // (1)

        float c[2][4][4];
#pragma unroll
        for (int mt = 0; mt < 2; mt++)
#pragma unroll
            for (int nt = 0; nt < 4; nt++)
#pragma unroll
                for (int e = 0; e < 4; e++) c[mt][nt][e] = 0.0f;
        gemm3(sb + E_AHI, sb + E_ALO, sb + E_WH, sb + E_WL, c, mrow0, ncol0, lane);

        // ---- bias + LN stats ----
        float s[2][2] = {{0, 0}, {0, 0}}, sq[2][2] = {{0, 0}, {0, 0}};
#pragma unroll
        for (int mt = 0; mt < 2; mt++)
#pragma unroll
            for (int nt = 0; nt < 4; nt++) {
                const int col0 = ncol0 + nt * 8 + (lane & 3) * 2;
                float v0 = c[mt][nt][0] + prm[col0];
                float v1 = c[mt][nt][1] + prm[col0 + 1];
                float v2 = c[mt][nt][2] + prm[col0];
                float v3 = c[mt][nt][3] + prm[col0 + 1];
                c[mt][nt][0] = v0; c[mt][nt][1] = v1;
                c[mt][nt][2] = v2; c[mt][nt][3] = v3;
                s[mt][0] += v0 + v1;  sq[mt][0] += v0 * v0 + v1 * v1;
                s[mt][1] += v2 + v3;  sq[mt][1] += v2 * v2 + v3 * v3;
            }
#pragma unroll
        for (int mt = 0; mt < 2; mt++)
#pragma unroll
            for (int rh = 0; rh < 2; rh++) {
                s[mt][rh] = qsum(s[mt][rh]);
                sq[mt][rh] = qsum(sq[mt][rh]);
            }
        if ((lane & 3) == 0) {
#pragma unroll
            for (int mt = 0; mt < 2; mt++)
#pragma unroll
                for (int rh = 0; rh < 2; rh++) {
                    const int row = mrow0 + mt * 16 + rh * 8 + (lane >> 2);
                    red[row * 8 + quar * 2]     = s[mt][rh];
                    red[row * 8 + quar * 2 + 1] = sq[mt][rh];
                }
        }
        __syncthreads();   // (2)

        // ---- normalize + ELU + dot(Wr2) ----
        float dacc[2][2] = {{0, 0}, {0, 0}};
#pragma unroll
        for (int mt = 0; mt < 2; mt++)
#pragma unroll
            for (int rh = 0; rh < 2; rh++) {
                const int row = mrow0 + mt * 16 + rh * 8 + (lane >> 2);
                const float ts = red[row * 8] + red[row * 8 + 2] + red[row * 8 + 4] + red[row * 8 + 6];
                const float tq = red[row * 8 + 1] + red[row * 8 + 3] + red[row * 8 + 5] + red[row * 8 + 7];
                const float m = ts * 0.0078125f;
                const float r = rsqrtf(tq * 0.0078125f - m * m + 1e-5f);
#pragma unroll
                for (int nt = 0; nt < 4; nt++) {
                    const int col0 = ncol0 + nt * 8 + (lane & 3) * 2;
                    const float y0 = elu1((c[mt][nt][2 * rh]     - m) * r * prm[128 + col0]     + prm[256 + col0]);
                    const float y1 = elu1((c[mt][nt][2 * rh + 1] - m) * r * prm[128 + col0 + 1] + prm[256 + col0 + 1]);
                    dacc[mt][rh] = fmaf(y0, prm[384 + col0], fmaf(y1, prm[384 + col0 + 1], dacc[mt][rh]));
                }
            }
#pragma unroll
        for (int mt = 0; mt < 2; mt++)
#pragma unroll
            for (int rh = 0; rh < 2; rh++) dacc[mt][rh] = qsum(dacc[mt][rh]);
        if ((lane & 3) == 0) {
#pragma unroll
            for (int mt = 0; mt < 2; mt++)
#pragma unroll
                for (int rh = 0; rh < 2; rh++) {
                    const int row = mrow0 + mt * 16 + rh * 8 + (lane >> 2);
                    rdd[row * 4 + quar] = dacc[mt][rh];
                }
        }
        __syncthreads();   // (3)
        if (tid < 128) {
            const long i = base + tid;
            if (i < nedges)
                out[i] = rdd[tid * 4] + rdd[tid * 4 + 1] + rdd[tid * 4 + 2] + rdd[tid * 4 + 3] + br2v;
        }
    }
}

// ---------------------------------------------------------------------------
__global__ __launch_bounds__(256)
void k_lse(float* __restrict__ out, int Nm1)
{
    __shared__ float red[8];
    __shared__ float bc;
    const int b = blockIdx.x;
    float* row = out + (long)b * Nm1;
    const int tid = threadIdx.x;

    float m = -3.4e38f;
    for (int i = tid; i < Nm1; i += 256) m = fmaxf(m, row[i]);
    m = warp_max(m);
    if ((tid & 31) == 0) red[tid >> 5] = m;
    __syncthreads();
    if (tid < 32) {
        float v = (tid < 8) ? red[tid] : -3.4e38f;
        v = warp_max(v);
        if (tid == 0) bc = v;
    }
    __syncthreads();
    const float M = bc;

    float s = 0.0f;
    for (int i = tid; i < Nm1; i += 256) s += __expf(row[i] - M);
    s = warp_sum(s);
    __syncthreads();
    if ((tid & 31) == 0) red[tid >> 5] = s;
    __syncthreads();
    if (tid < 32) {
        float v = (tid < 8) ? red[tid] : 0.0f;
        v = warp_sum(v);
        if (tid == 0) bc = M + __logf(v);
    }
    __syncthreads();
    const float lse = bc;
    for (int i = tid; i < Nm1; i += 256) row[i] -= lse;
}

// ---------------------------------------------------------------------------
extern "C" void kernel_launch(void* const* d_in, const int* in_sizes, int n_in,
                              void* d_out, int out_size)
{
    const float* x    = (const float*)d_in[0];
    const int*   pidx = (const int*)  d_in[1];
    const float* W1   = (const float*)d_in[2];
    const float* b1   = (const float*)d_in[3];
    const float* g1   = (const float*)d_in[4];
    const float* be1  = (const float*)d_in[5];
    const float* W2   = (const float*)d_in[6];
    const float* b2   = (const float*)d_in[7];
    const float* g2   = (const float*)d_in[8];
    const float* be2  = (const float*)d_in[9];
    const float* Wr1  = (const float*)d_in[10];
    const float* br1  = (const float*)d_in[11];
    const float* gr1  = (const float*)d_in[12];
    const float* ber1 = (const float*)d_in[13];
    const float* Wr2  = (const float*)d_in[14];
    const float* br2  = (const float*)d_in[15];
    float* out = (float*)d_out;

    const int nrows  = in_sizes[0] / 128;     // B*N
    const int nedges = in_sizes[1];           // B*(N-1)
    const int B      = nrows - nedges;
    const int N      = nrows / B;
    const int Nm1    = N - 1;

    cudaFuncSetAttribute(k_mlp,  cudaFuncAttributeMaxDynamicSharedMemorySize, M_TOT);
    cudaFuncSetAttribute(k_edge, cudaFuncAttributeMaxDynamicSharedMemorySize, E_TOT);

    k_mlp<<<152, NT, M_TOT>>>(x, W1, b1, g1, be1, W2, b2, g2, be2, nrows);
    k_edge<<<152, NT, E_TOT>>>(pidx, Wr1, br1, gr1, ber1, Wr2, br2,
                               out, nedges, Nm1, N);
    k_lse<<<B, 256>>>(out, Nm1);
}

// round 17
// speedup vs baseline: 1.1261x; 1.1261x over previous
#include <cuda_runtime.h>
#include <cuda_bf16.h>
#include <math.h>
#include <stdint.h>

#define SA 272u   // padded smem row stride in bytes (128 bf16 + 16B pad)
#define NT 512    // threads per CTA (16 warps, 4 row-groups)

// f32 h after stage 2 (needed for the irregular parent gather). 128 MiB static.
__device__ float g_H[64u * 4096u * 128u];

// ---------------------------------------------------------------------------
static __device__ __forceinline__ uint32_t s2u(const void* p) {
    uint32_t a;
    asm("{ .reg .u64 t; cvta.to.shared.u64 t, %1; cvt.u32.u64 %0, t; }" : "=r"(a) : "l"(p));
    return a;
}
static __device__ __forceinline__ void barg(int id) {
    asm volatile("bar.sync %0, 128;" :: "r"(id) : "memory");
}
static __device__ __forceinline__ void pfL2(const void* p) {
    asm volatile("prefetch.global.L2 [%0];" :: "l"(p));
}
static __device__ __forceinline__ void ldsm4(uint32_t& r0, uint32_t& r1, uint32_t& r2,
                                             uint32_t& r3, uint32_t addr) {
    asm volatile("ldmatrix.sync.aligned.m8n8.x4.shared.b16 {%0,%1,%2,%3}, [%4];"
                 : "=r"(r0), "=r"(r1), "=r"(r2), "=r"(r3) : "r"(addr));
}
static __device__ __forceinline__ void mma16816(float* c, const uint32_t* a,
                                                uint32_t b0, uint32_t b1) {
    asm volatile("mma.sync.aligned.m16n8k16.row.col.f32.bf16.bf16.f32 "
                 "{%0,%1,%2,%3},{%4,%5,%6,%7},{%8,%9},{%0,%1,%2,%3};"
                 : "+f"(c[0]), "+f"(c[1]), "+f"(c[2]), "+f"(c[3])
                 : "r"(a[0]), "r"(a[1]), "r"(a[2]), "r"(a[3]), "r"(b0), "r"(b1));
}
// fast ELU: exp via single MUFU.EX2 (__expf). |abs err| ~1e-7, fine vs 1e-3 gate.
static __device__ __forceinline__ float elu1(float v) {
    return v > 0.0f ? v : (__expf(v) - 1.0f);
}
static __device__ __forceinline__ uint32_t pack2(__nv_bfloat16 a, __nv_bfloat16 b) {
    __nv_bfloat162 t = __halves2bfloat162(a, b);
    return *(uint32_t*)&t;
}
static __device__ __forceinline__ void split2(float a, float b, uint32_t& hi, uint32_t& lo) {
    __nv_bfloat16 ha = __float2bfloat16(a), hb = __float2bfloat16(b);
    __nv_bfloat16 la = __float2bfloat16(a - __bfloat162float(ha));
    __nv_bfloat16 lb = __float2bfloat16(b - __bfloat162float(hb));
    hi = pack2(ha, hb);
    lo = pack2(la, lb);
}
__device__ __forceinline__ float warp_sum(float v) {
#pragma unroll
    for (int o = 16; o; o >>= 1) v += __shfl_xor_sync(0xffffffffu, v, o);
    return v;
}
__device__ __forceinline__ float warp_max(float v) {
#pragma unroll
    for (int o = 16; o; o >>= 1) v = fmaxf(v, __shfl_xor_sync(0xffffffffu, v, o));
    return v;
}
static __device__ __forceinline__ float qsum(float v) {
    v += __shfl_xor_sync(0xffffffffu, v, 1);
    v += __shfl_xor_sync(0xffffffffu, v, 2);
    return v;
}

// Merged 3-product hi/lo GEMM over K=128. Single kt loop, 64 ldsm4 total.
// All 8 kt-fragments loaded before the 24-MMA stream (latency hiding).
static __device__ __forceinline__ void gemm3(uint32_t aHi, uint32_t aLo,
                                             uint32_t wHi, uint32_t wLo,
                                             float c[2][4][4], int mrow0, int ncol0,
                                             int lane) {
    const int arow = ((lane >> 3) & 1) * 8 + (lane & 7);
    const int acol = ((lane >> 4) & 1) * 8;
    const int brow = ((lane >> 4) & 1) * 8 + (lane & 7);
    const int bcol = ((lane >> 3) & 1) * 8;
#pragma unroll
    for (int kt = 0; kt < 8; kt++) {
        uint32_t bh[4][2], bl[4][2];
#pragma unroll
        for (int np = 0; np < 2; np++) {
            const uint32_t boffs = (uint32_t)(ncol0 + np * 16 + brow) * SA + (kt * 16 + bcol) * 2;
            ldsm4(bh[2 * np][0], bh[2 * np][1], bh[2 * np + 1][0], bh[2 * np + 1][1], wHi + boffs);
            ldsm4(bl[2 * np][0], bl[2 * np][1], bl[2 * np + 1][0], bl[2 * np + 1][1], wLo + boffs);
        }
        uint32_t ah[2][4], al[2][4];
#pragma unroll
        for (int mt = 0; mt < 2; mt++) {
            const uint32_t aoffs = (uint32_t)(mrow0 + mt * 16 + arow) * SA + (kt * 16 + acol) * 2;
            ldsm4(ah[mt][0], ah[mt][1], ah[mt][2], ah[mt][3], aHi + aoffs);
            ldsm4(al[mt][0], al[mt][1], al[mt][2], al[mt][3], aLo + aoffs);
        }
#pragma unroll
        for (int mt = 0; mt < 2; mt++) {
#pragma unroll
            for (int nt = 0; nt < 4; nt++) mma16816(c[mt][nt], ah[mt], bh[nt][0], bh[nt][1]);
#pragma unroll
            for (int nt = 0; nt < 4; nt++) mma16816(c[mt][nt], al[mt], bh[nt][0], bh[nt][1]);
#pragma unroll
            for (int nt = 0; nt < 4; nt++) mma16816(c[mt][nt], ah[mt], bl[nt][0], bl[nt][1]);
        }
    }
}

// ---------------------------------------------------------------------------
// k_mlp smem layout (bytes)
#define M_AHI 0u
#define M_ALO 34816u
#define M_W1H 69632u
#define M_W1L 104448u
#define M_W2H 139264u
#define M_W2L 174080u
#define M_PRM 208896u
#define M_RED 211968u
#define M_TOT 216064u

__global__ __launch_bounds__(NT, 1)
void k_mlp(const float* __restrict__ x,
           const float* __restrict__ W1, const float* __restrict__ b1,
           const float* __restrict__ g1, const float* __restrict__ be1,
           const float* __restrict__ W2, const float* __restrict__ b2,
           const float* __restrict__ g2, const float* __restrict__ be2,
           int nrows)
{
    extern __shared__ char smem[];
    const uint32_t sb = s2u(smem);
    float* prm = (float*)(smem + M_PRM);
    float* red = (float*)(smem + M_RED);
    const int tid = threadIdx.x, w = tid >> 5, lane = tid & 31;
    const int grp = tid >> 7;                // row-group 0..3
    const int tig = tid & 127;               // tid within group
    const int mrow0 = grp * 32, quar = w & 3, ncol0 = quar * 32;
    const int barid = 1 + grp;

    // Weights: Wt[n][k] bf16 hi/lo, padded rows
    for (int idx = tid; idx < 16384; idx += NT) {
        const int k = idx >> 7, n = idx & 127;
        float wv = W1[idx];
        __nv_bfloat16 h = __float2bfloat16(wv);
        *(__nv_bfloat16*)(smem + M_W1H + n * SA + k * 2) = h;
        *(__nv_bfloat16*)(smem + M_W1L + n * SA + k * 2) = __float2bfloat16(wv - __bfloat162float(h));
        wv = W2[idx];
        h = __float2bfloat16(wv);
        *(__nv_bfloat16*)(smem + M_W2H + n * SA + k * 2) = h;
        *(__nv_bfloat16*)(smem + M_W2L + n * SA + k * 2) = __float2bfloat16(wv - __bfloat162float(h));
    }
    if (tid < 128) {
        prm[tid]       = b1[tid];
        prm[128 + tid] = g1[tid];
        prm[256 + tid] = be1[tid];
        prm[384 + tid] = b2[tid];
        prm[512 + tid] = g2[tid];
        prm[640 + tid] = be2[tid];
    }
    __syncthreads();

    const float4* x4 = (const float4*)x;
    const int ntiles = nrows >> 7;

    for (int t = blockIdx.x; t < ntiles; t += gridDim.x) {
        const long row0g = (long)t << 7;

        // ---- group loads its 32 rows of x -> A_hi/A_lo ----
        for (int i = tig; i < 1024; i += 128) {
            const int r = i >> 5, c4 = i & 31;       // r in [0,32)
            const float4 v = x4[(row0g + mrow0 + r) * 32 + c4];
            uint2 uh, ul;
            split2(v.x, v.y, uh.x, ul.x);
            split2(v.z, v.w, uh.y, ul.y);
            *(uint2*)(smem + M_AHI + (mrow0 + r) * SA + c4 * 8) = uh;
            *(uint2*)(smem + M_ALO + (mrow0 + r) * SA + c4 * 8) = ul;
        }
        // L2 prefetch of this group's next x rows (one 128B line per thread)
        {
            const int t2 = t + gridDim.x;
            if (t2 < ntiles)
                pfL2(x + (((long)t2 << 7) + mrow0) * 128 + tig * 32);
        }
        barg(barid);   // (1)

        // ---- GEMM1 ----
        float c[2][4][4];
#pragma unroll
        for (int mt = 0; mt < 2; mt++)
#pragma unroll
            for (int nt = 0; nt < 4; nt++)
#pragma unroll
                for (int e = 0; e < 4; e++) c[mt][nt][e] = 0.0f;
        gemm3(sb + M_AHI, sb + M_ALO, sb + M_W1H, sb + M_W1L, c, mrow0, ncol0, lane);

        // ---- epilogue 1: bias + LN stats ----
        {
            float s[2][2] = {{0, 0}, {0, 0}}, sq[2][2] = {{0, 0}, {0, 0}};
#pragma unroll
            for (int mt = 0; mt < 2; mt++)
#pragma unroll
                for (int nt = 0; nt < 4; nt++) {
                    const int col0 = ncol0 + nt * 8 + (lane & 3) * 2;
                    float v0 = c[mt][nt][0] + prm[col0];
                    float v1 = c[mt][nt][1] + prm[col0 + 1];
                    float v2 = c[mt][nt][2] + prm[col0];
                    float v3 = c[mt][nt][3] + prm[col0 + 1];
                    c[mt][nt][0] = v0; c[mt][nt][1] = v1;
                    c[mt][nt][2] = v2; c[mt][nt][3] = v3;
                    s[mt][0] += v0 + v1;  sq[mt][0] += v0 * v0 + v1 * v1;
                    s[mt][1] += v2 + v3;  sq[mt][1] += v2 * v2 + v3 * v3;
                }
#pragma unroll
            for (int mt = 0; mt < 2; mt++)
#pragma unroll
                for (int rh = 0; rh < 2; rh++) {
                    s[mt][rh] = qsum(s[mt][rh]);
                    sq[mt][rh] = qsum(sq[mt][rh]);
                }
            if ((lane & 3) == 0) {
#pragma unroll
                for (int mt = 0; mt < 2; mt++)
#pragma unroll
                    for (int rh = 0; rh < 2; rh++) {
                        const int row = mrow0 + mt * 16 + rh * 8 + (lane >> 2);
                        red[row * 8 + quar * 2]     = s[mt][rh];
                        red[row * 8 + quar * 2 + 1] = sq[mt][rh];
                    }
            }
            barg(barid);   // (2)
            float mu[2][2], rs[2][2];
#pragma unroll
            for (int mt = 0; mt < 2; mt++)
#pragma unroll
                for (int rh = 0; rh < 2; rh++) {
                    const int row = mrow0 + mt * 16 + rh * 8 + (lane >> 2);
                    const float ts = red[row * 8] + red[row * 8 + 2] + red[row * 8 + 4] + red[row * 8 + 6];
                    const float tq = red[row * 8 + 1] + red[row * 8 + 3] + red[row * 8 + 5] + red[row * 8 + 7];
                    const float m = ts * 0.0078125f;
                    mu[mt][rh] = m;
                    rs[mt][rh] = rsqrtf(tq * 0.0078125f - m * m + 1e-5f);
                }
            // normalize + ELU -> A_hi/A_lo
#pragma unroll
            for (int mt = 0; mt < 2; mt++)
#pragma unroll
                for (int nt = 0; nt < 4; nt++) {
                    const int col0 = ncol0 + nt * 8 + (lane & 3) * 2;
#pragma unroll
                    for (int rh = 0; rh < 2; rh++) {
                        const int row = mrow0 + mt * 16 + rh * 8 + (lane >> 2);
                        const float y0 = elu1((c[mt][nt][2 * rh]     - mu[mt][rh]) * rs[mt][rh] * prm[128 + col0]     + prm[256 + col0]);
                        const float y1 = elu1((c[mt][nt][2 * rh + 1] - mu[mt][rh]) * rs[mt][rh] * prm[128 + col0 + 1] + prm[256 + col0 + 1]);
                        uint32_t hh, ll;
                        split2(y0, y1, hh, ll);
                        *(uint32_t*)(smem + M_AHI + row * SA + col0 * 2) = hh;
                        *(uint32_t*)(smem + M_ALO + row * SA + col0 * 2) = ll;
                    }
                }
        }
        barg(barid);   // (3)

        // ---- GEMM2 ----
#pragma unroll
        for (int mt = 0; mt < 2; mt++)
#pragma unroll
            for (int nt = 0; nt < 4; nt++)
#pragma unroll
                for (int e = 0; e < 4; e++) c[mt][nt][e] = 0.0f;
        gemm3(sb + M_AHI, sb + M_ALO, sb + M_W2H, sb + M_W2L, c, mrow0, ncol0, lane);

        // ---- epilogue 2: bias + LN + ELU -> g_H (direct) ----
        {
            float s[2][2] = {{0, 0}, {0, 0}}, sq[2][2] = {{0, 0}, {0, 0}};
#pragma unroll
            for (int mt = 0; mt < 2; mt++)
#pragma unroll
                for (int nt = 0; nt < 4; nt++) {
                    const int col0 = ncol0 + nt * 8 + (lane & 3) * 2;
                    float v0 = c[mt][nt][0] + prm[384 + col0];
                    float v1 = c[mt][nt][1] + prm[384 + col0 + 1];
                    float v2 = c[mt][nt][2] + prm[384 + col0];
                    float v3 = c[mt][nt][3] + prm[384 + col0 + 1];
                    c[mt][nt][0] = v0; c[mt][nt][1] = v1;
                    c[mt][nt][2] = v2; c[mt][nt][3] = v3;
                    s[mt][0] += v0 + v1;  sq[mt][0] += v0 * v0 + v1 * v1;
                    s[mt][1] += v2 + v3;  sq[mt][1] += v2 * v2 + v3 * v3;
                }
#pragma unroll
            for (int mt = 0; mt < 2; mt++)
#pragma unroll
                for (int rh = 0; rh < 2; rh++) {
                    s[mt][rh] = qsum(s[mt][rh]);
                    sq[mt][rh] = qsum(sq[mt][rh]);
                }
            if ((lane & 3) == 0) {
#pragma unroll
                for (int mt = 0; mt < 2; mt++)
#pragma unroll
                    for (int rh = 0; rh < 2; rh++) {
                        const int row = mrow0 + mt * 16 + rh * 8 + (lane >> 2);
                        red[row * 8 + quar * 2]     = s[mt][rh];
                        red[row * 8 + quar * 2 + 1] = sq[mt][rh];
                    }
            }
            barg(barid);   // (4) — also signals GEMM2 A-reads complete
#pragma unroll
            for (int mt = 0; mt < 2; mt++)
#pragma unroll
                for (int rh = 0; rh < 2; rh++) {
                    const int row = mrow0 + mt * 16 + rh * 8 + (lane >> 2);
                    const float ts = red[row * 8] + red[row * 8 + 2] + red[row * 8 + 4] + red[row * 8 + 6];
                    const float tq = red[row * 8 + 1] + red[row * 8 + 3] + red[row * 8 + 5] + red[row * 8 + 7];
                    const float m = ts * 0.0078125f;
                    const float r = rsqrtf(tq * 0.0078125f - m * m + 1e-5f);
                    float* grow = g_H + (row0g + row) * 128;
#pragma unroll
                    for (int nt = 0; nt < 4; nt++) {
                        const int col0 = ncol0 + nt * 8 + (lane & 3) * 2;
                        const float o0 = elu1((c[mt][nt][2 * rh]     - m) * r * prm[512 + col0]     + prm[640 + col0]);
                        const float o1 = elu1((c[mt][nt][2 * rh + 1] - m) * r * prm[512 + col0 + 1] + prm[640 + col0 + 1]);
                        *(float2*)(grow + col0) = make_float2(o0, o1);
                    }
                }
        }
        // next-tile A overwrite is safe: barrier (4) ordered all GEMM2 reads.
    }
}

// ---------------------------------------------------------------------------
// k_edge smem layout (whole-CTA structure)
#define E_AHI 0u
#define E_ALO 34816u
#define E_WH  69632u
#define E_WL  104448u
#define E_PRM 139264u
#define E_RED 141312u
#define E_RDD 145408u
#define E_TOT 147456u

__global__ __launch_bounds__(NT, 1)
void k_edge(const int* __restrict__ pidx,
            const float* __restrict__ Wr1, const float* __restrict__ br1,
            const float* __restrict__ gr1, const float* __restrict__ ber1,
            const float* __restrict__ Wr2, const float* __restrict__ br2,
            float* __restrict__ out, int nedges, int Nm1, int N)
{
    extern __shared__ char smem[];
    const uint32_t sb = s2u(smem);
    float* prm = (float*)(smem + E_PRM);
    float* red = (float*)(smem + E_RED);
    float* rdd = (float*)(smem + E_RDD);
    const int tid = threadIdx.x, w = tid >> 5, lane = tid & 31;
    const int mrow0 = (w >> 2) * 32, quar = w & 3, ncol0 = quar * 32;

    for (int idx = tid; idx < 16384; idx += NT) {
        const int k = idx >> 7, n = idx & 127;
        const float wv = Wr1[idx];
        const __nv_bfloat16 h = __float2bfloat16(wv);
        *(__nv_bfloat16*)(smem + E_WH + n * SA + k * 2) = h;
        *(__nv_bfloat16*)(smem + E_WL + n * SA + k * 2) = __float2bfloat16(wv - __bfloat162float(h));
    }
    if (tid < 128) {
        prm[tid]       = br1[tid];
        prm[128 + tid] = gr1[tid];
        prm[256 + tid] = ber1[tid];
        prm[384 + tid] = Wr2[tid];
    }
    __syncthreads();

    const float br2v = br2[0];
    const float4* gh4 = (const float4*)g_H;
    const int ntiles = (nedges + 127) >> 7;
    const bool fastdiv = (Nm1 >= 128);   // a 128-row tile crosses <=1 batch boundary

    for (int t = blockIdx.x; t < ntiles; t += gridDim.x) {
        const int base = t << 7;
        const int b0 = base / Nm1;                   // one division per tile
        const int thr = (b0 + 1) * Nm1 - base;       // rows >= thr are batch b0+1

        // ---- gather + max -> A_hi/A_lo (warp w handles rows 8w..8w+7) ----
#pragma unroll
        for (int r8 = 0; r8 < 8; r8++) {
            const int row = w * 8 + r8;
            int i = base + row;
            if (i >= nedges) i = nedges - 1;
            const int rr = i - base;                 // clamped row offset
            const int b = fastdiv ? (b0 + (rr >= thr ? 1 : 0)) : (i / Nm1);
            const int n = i - b * Nm1;
            const long crow = (long)b * N + n;
            const long prow = (long)pidx[i];
            const float4 c4v = gh4[crow * 32 + lane];
            const float4 p4v = gh4[prow * 32 + lane];
            uint2 uh, ul;
            split2(fmaxf(c4v.x, p4v.x), fmaxf(c4v.y, p4v.y), uh.x, ul.x);
            split2(fmaxf(c4v.z, p4v.z), fmaxf(c4v.w, p4v.w), uh.y, ul.y);
            *(uint2*)(smem + E_AHI + row * SA + lane * 8) = uh;
            *(uint2*)(smem + E_ALO + row * SA + lane * 8) = ul;
        }

        // ---- L2 prefetch of next tile's child+parent rows (overlaps GEMM) ----
        {
            const int t2 = t + gridDim.x;
            if (t2 < ntiles) {
                const int base2 = t2 << 7;
                const int b20 = base2 / Nm1;
                const int thr2 = (b20 + 1) * Nm1 - base2;
                const int row2 = w * 8 + (lane >> 2);    // 8 rows across warp
                int i2 = base2 + row2;
                if (i2 >= nedges) i2 = nedges - 1;
                const int rr2 = i2 - base2;
                const int b2 = fastdiv ? (b20 + (rr2 >= thr2 ? 1 : 0)) : (i2 / Nm1);
                const int n2 = i2 - b2 * Nm1;
                const long crow2 = (long)b2 * N + n2;
                const long prow2 = (long)pidx[i2];
                const int line = (lane & 3) * 32;        // 4 lines x 128B per row
                pfL2(g_H + crow2 * 128 + line);
                pfL2(g_H + prow2 * 128 + line);
            }
        }
        __syncthreads();   // (1)

        float c[2][4][4];
#pragma unroll
        for (int mt = 0; mt < 2; mt++)
#pragma unroll
            for (int nt = 0; nt < 4; nt++)
#pragma unroll
                for (int e = 0; e < 4; e++) c[mt][nt][e] = 0.0f;
        gemm3(sb + E_AHI, sb + E_ALO, sb + E_WH, sb + E_WL, c, mrow0, ncol0, lane);

        // ---- bias + LN stats ----
        float s[2][2] = {{0, 0}, {0, 0}}, sq[2][2] = {{0, 0}, {0, 0}};
#pragma unroll
        for (int mt = 0; mt < 2; mt++)
#pragma unroll
            for (int nt = 0; nt < 4; nt++) {
                const int col0 = ncol0 + nt * 8 + (lane & 3) * 2;
                float v0 = c[mt][nt][0] + prm[col0];
                float v1 = c[mt][nt][1] + prm[col0 + 1];
                float v2 = c[mt][nt][2] + prm[col0];
                float v3 = c[mt][nt][3] + prm[col0 + 1];
                c[mt][nt][0] = v0; c[mt][nt][1] = v1;
                c[mt][nt][2] = v2; c[mt][nt][3] = v3;
                s[mt][0] += v0 + v1;  sq[mt][0] += v0 * v0 + v1 * v1;
                s[mt][1] += v2 + v3;  sq[mt][1] += v2 * v2 + v3 * v3;
            }
#pragma unroll
        for (int mt = 0; mt < 2; mt++)
#pragma unroll
            for (int rh = 0; rh < 2; rh++) {
                s[mt][rh] = qsum(s[mt][rh]);
                sq[mt][rh] = qsum(sq[mt][rh]);
            }
        if ((lane & 3) == 0) {
#pragma unroll
            for (int mt = 0; mt < 2; mt++)
#pragma unroll
                for (int rh = 0; rh < 2; rh++) {
                    const int row = mrow0 + mt * 16 + rh * 8 + (lane >> 2);
                    red[row * 8 + quar * 2]     = s[mt][rh];
                    red[row * 8 + quar * 2 + 1] = sq[mt][rh];
                }
        }
        __syncthreads();   // (2)

        // ---- normalize + ELU + dot(Wr2) ----
        float dacc[2][2] = {{0, 0}, {0, 0}};
#pragma unroll
        for (int mt = 0; mt < 2; mt++)
#pragma unroll
            for (int rh = 0; rh < 2; rh++) {
                const int row = mrow0 + mt * 16 + rh * 8 + (lane >> 2);
                const float ts = red[row * 8] + red[row * 8 + 2] + red[row * 8 + 4] + red[row * 8 + 6];
                const float tq = red[row * 8 + 1] + red[row * 8 + 3] + red[row * 8 + 5] + red[row * 8 + 7];
                const float m = ts * 0.0078125f;
                const float r = rsqrtf(tq * 0.0078125f - m * m + 1e-5f);
#pragma unroll
                for (int nt = 0; nt < 4; nt++) {
                    const int col0 = ncol0 + nt * 8 + (lane & 3) * 2;
                    const float y0 = elu1((c[mt][nt][2 * rh]     - m) * r * prm[128 + col0]     + prm[256 + col0]);
                    const float y1 = elu1((c[mt][nt][2 * rh + 1] - m) * r * prm[128 + col0 + 1] + prm[256 + col0 + 1]);
                    dacc[mt][rh] = fmaf(y0, prm[384 + col0], fmaf(y1, prm[384 + col0 + 1], dacc[mt][rh]));
                }
            }
#pragma unroll
        for (int mt = 0; mt < 2; mt++)
#pragma unroll
            for (int rh = 0; rh < 2; rh++) dacc[mt][rh] = qsum(dacc[mt][rh]);
        if ((lane & 3) == 0) {
#pragma unroll
            for (int mt = 0; mt < 2; mt++)
#pragma unroll
                for (int rh = 0; rh < 2; rh++) {
                    const int row = mrow0 + mt * 16 + rh * 8 + (lane >> 2);
                    rdd[row * 4 + quar] = dacc[mt][rh];
                }
        }
        __syncthreads();   // (3)
        if (tid < 128) {
            const int i = base + tid;
            if (i < nedges)
                out[i] = rdd[tid * 4] + rdd[tid * 4 + 1] + rdd[tid * 4 + 2] + rdd[tid * 4 + 3] + br2v;
        }
    }
}

// ---------------------------------------------------------------------------
__global__ __launch_bounds__(256)
void k_lse(float* __restrict__ out, int Nm1)
{
    __shared__ float red[8];
    __shared__ float bc;
    const int b = blockIdx.x;
    float* row = out + (long)b * Nm1;
    const int tid = threadIdx.x;

    float m = -3.4e38f;
    for (int i = tid; i < Nm1; i += 256) m = fmaxf(m, row[i]);
    m = warp_max(m);
    if ((tid & 31) == 0) red[tid >> 5] = m;
    __syncthreads();
    if (tid < 32) {
        float v = (tid < 8) ? red[tid] : -3.4e38f;
        v = warp_max(v);
        if (tid == 0) bc = v;
    }
    __syncthreads();
    const float M = bc;

    float s = 0.0f;
    for (int i = tid; i < Nm1; i += 256) s += __expf(row[i] - M);
    s = warp_sum(s);
    __syncthreads();
    if ((tid & 31) == 0) red[tid >> 5] = s;
    __syncthreads();
    if (tid < 32) {
        float v = (tid < 8) ? red[tid] : 0.0f;
        v = warp_sum(v);
        if (tid == 0) bc = M + __logf(v);
    }
    __syncthreads();
    const float lse = bc;
    for (int i = tid; i < Nm1; i += 256) row[i] -= lse;
}

// ---------------------------------------------------------------------------
extern "C" void kernel_launch(void* const* d_in, const int* in_sizes, int n_in,
                              void* d_out, int out_size)
{
    const float* x    = (const float*)d_in[0];
    const int*   pidx = (const int*)  d_in[1];
    const float* W1   = (const float*)d_in[2];
    const float* b1   = (const float*)d_in[3];
    const float* g1   = (const float*)d_in[4];
    const float* be1  = (const float*)d_in[5];
    const float* W2   = (const float*)d_in[6];
    const float* b2   = (const float*)d_in[7];
    const float* g2   = (const float*)d_in[8];
    const float* be2  = (const float*)d_in[9];
    const float* Wr1  = (const float*)d_in[10];
    const float* br1  = (const float*)d_in[11];
    const float* gr1  = (const float*)d_in[12];
    const float* ber1 = (const float*)d_in[13];
    const float* Wr2  = (const float*)d_in[14];
    const float* br2  = (const float*)d_in[15];
    float* out = (float*)d_out;

    const int nrows  = in_sizes[0] / 128;     // B*N
    const int nedges = in_sizes[1];           // B*(N-1)
    const int B      = nrows - nedges;
    const int N      = nrows / B;
    const int Nm1    = N - 1;

    cudaFuncSetAttribute(k_mlp,  cudaFuncAttributeMaxDynamicSharedMemorySize, M_TOT);
    cudaFuncSetAttribute(k_edge, cudaFuncAttributeMaxDynamicSharedMemorySize, E_TOT);

    k_mlp<<<152, NT, M_TOT>>>(x, W1, b1, g1, be1, W2, b2, g2, be2, nrows);
    k_edge<<<152, NT, E_TOT>>>(pidx, Wr1, br1, gr1, ber1, Wr2, br2,
                               out, nedges, Nm1, N);
    k_lse<<<B, 256>>>(out, Nm1);
}